// round 12
// baseline (speedup 1.0000x reference)
#include <cuda_runtime.h>
#include <math.h>

#define HH 256
#define WW 512
#define CC 16
#define ND 32
#define HW (HH * WW)
#define NDHW (ND * HW)
#define BASELINE_V 0.24f
#define WTILE 64
#define SROW 67            // padded smem row stride in float4
#define MAX_ROWS 43        // analytic bound: max span 38.8 rows + 4 guard

// Horizontally pre-interpolated y, 4 channel-chunk planes
__device__ float4 g_Z[4 * HW];
// Precomputed vertical sample position per (d,h,w)
__device__ float g_iy[NDHW];

// iy via cancellation-free identity: atan(u) - theta = atan(B*cos/(d + B*sin))
__device__ __forceinline__ float iy_fast(float dep, float Bs, float Bc, float hf)
{
    float dth = atanf(Bc / (dep + Bs));                      // > 0, small arg
    float ypx = hf + dth * ((float)HH / 3.14159265358979323846f);
    return ypx * ((float)HH / ((float)HH - 1.0f)) - 0.5f;
}

// ---------------- Kernel 1: merged prologue ----------------
// 4*HW threads: thread (chunk, p) does hinterp of its chunk at pixel p,
// plus iy for the 8 disparities d in [chunk*8, chunk*8+8).
__global__ __launch_bounds__(256) void prologue_kernel(const float* __restrict__ y,
                                                       const float* __restrict__ depth)
{
    int t = blockIdx.x * 256 + threadIdx.x;   // 4*HW threads
    int p = t & (HW - 1);
    int chunk = t >> 17;
    int w = p & (WW - 1);
    int h = p >> 9;
    int rbase = p - w;

    const float PI = 3.14159265358979323846f;
    float hf = (float)h;
    float theta = (hf + 0.5f) * (PI / (float)HH) - 0.5f * PI;
    float st, ct;
    sincosf(theta, &st, &ct);
    float Bs = BASELINE_V * st, Bc = BASELINE_V * ct;

    // --- horizontal interp for this chunk ---
    float ix = (float)w * ((float)WW / ((float)WW - 1.0f)) - 0.5f;
    float fx0 = floorf(ix);
    float wx  = ix - fx0;
    int xi0 = (int)fx0, xi1 = xi0 + 1;
    float w0x = (xi0 >= 0 && xi0 < WW) ? (1.0f - wx) : 0.0f;
    float w1x = (xi1 >= 0 && xi1 < WW) ? wx : 0.0f;
    int xc0 = min(max(xi0, 0), WW - 1);
    int xc1 = min(max(xi1, 0), WW - 1);

    float v[4];
    #pragma unroll
    for (int c = 0; c < 4; c++) {
        const float* yc = y + (size_t)(chunk * 4 + c) * HW + rbase;
        v[c] = w0x * __ldg(yc + xc0) + w1x * __ldg(yc + xc1);
    }
    g_Z[chunk * HW + p] = make_float4(v[0], v[1], v[2], v[3]);

    // --- iy for this chunk's 8 disparities ---
    int d0 = chunk * 8;
    #pragma unroll
    for (int k = 0; k < 8; k++) {
        float dep = __ldg(depth + (size_t)(d0 + k) * HW + p);
        g_iy[(size_t)(d0 + k) * HW + p] = iy_fast(dep, Bs, Bc, hf);
    }
}

// ---------------- Kernel 2: smem-staged fused kernel ----------------
// grid (4 chunks * 8 wtiles, HH). Block 256 = 16 wg (4 w) x 16 dg (2 d each).
__global__ __launch_bounds__(256, 5) void fused_cv_kernel(const float* __restrict__ x,
                                                          float* __restrict__ out)
{
    __shared__ float4 s_Z[MAX_ROWS * SROW];   // ~45.0 KB -> 5 CTAs/SM

    int chunk = blockIdx.x & 3;
    int wt    = blockIdx.x >> 2;
    int h     = blockIdx.y;
    int wg    = threadIdx.x & 15;
    int dg    = threadIdx.x >> 4;              // 0..15
    int wbase = wt * WTILE;
    int w0    = wbase + wg * 4;
    int c0    = chunk * 4;

    const float PI = 3.14159265358979323846f;
    float hf = (float)h;
    float theta = (hf + 0.5f) * (PI / (float)HH) - 0.5f * PI;
    float st, ct;
    sincosf(theta, &st, &ct);
    float Bs = BASELINE_V * st, Bc = BASELINE_V * ct;

    // row range for depth in [0.5, 8] (iy monotone decreasing in depth)
    float iy_min = iy_fast(8.0f, Bs, Bc, hf);
    float iy_max = iy_fast(0.5f, Bs, Bc, hf);
    int r_lo = min(max((int)floorf(iy_min) - 1, 0), HH - 1);
    int r_hi = min(max((int)floorf(iy_max) + 2, 0), HH - 1);
    int nrows = min(r_hi - r_lo + 1, MAX_ROWS);

    int hw0 = h * WW + w0;

    // prefetch iy for both d's (latency overlaps with staging below)
    float4 iy4_0 = *(const float4*)(g_iy + (size_t)(dg * 2 + 0) * HW + hw0);
    float4 iy4_1 = *(const float4*)(g_iy + (size_t)(dg * 2 + 1) * HW + hw0);

    // cooperative staging of Z rows for this wtile
    const float4* __restrict__ plane = g_Z + (size_t)chunk * HW;
    for (int i = threadIdx.x; i < nrows * WTILE; i += 256) {
        int row = i >> 6;
        int col = i & (WTILE - 1);
        s_Z[row * SROW + col] = __ldg(plane + (size_t)(r_lo + row) * WW + wbase + col);
    }

    // vertical interp params (ALU overlaps other warps' staging)
    float wA[2][4], wB[2][4];
    int   o0[2][4], o1[2][4];
    #pragma unroll
    for (int k = 0; k < 2; k++) {
        float4 iy4 = k ? iy4_1 : iy4_0;
        #pragma unroll
        for (int j = 0; j < 4; j++) {
            float iy = (j == 0) ? iy4.x : (j == 1) ? iy4.y : (j == 2) ? iy4.z : iy4.w;
            float fy0 = floorf(iy);
            float wy  = iy - fy0;
            int yi0 = (int)fy0, yi1 = yi0 + 1;
            wA[k][j] = (yi0 >= 0 && yi0 < HH) ? (1.0f - wy) : 0.0f;
            wB[k][j] = (yi1 >= 0 && yi1 < HH) ? wy : 0.0f;
            int yc0 = min(max(yi0, 0), HH - 1);
            int yc1 = min(max(yi1, 0), HH - 1);
            int ry0 = min(max(yc0 - r_lo, 0), nrows - 1);
            int ry1 = min(max(yc1 - r_lo, 0), nrows - 1);
            o0[k][j] = ry0 * SROW + wg * 4 + j;
            o1[k][j] = ry1 * SROW + wg * 4 + j;
        }
    }

    __syncthreads();

    #pragma unroll
    for (int k = 0; k < 2; k++) {
        int d = dg * 2 + k;
        float oc[4][4];
        #pragma unroll
        for (int j = 0; j < 4; j++) {
            float4 a = s_Z[o0[k][j]];
            float4 b = s_Z[o1[k][j]];
            float fA = wA[k][j], fB = wB[k][j];
            oc[0][j] = fmaf(fA, a.x, fB * b.x);
            oc[1][j] = fmaf(fA, a.y, fB * b.y);
            oc[2][j] = fmaf(fA, a.z, fB * b.z);
            oc[3][j] = fmaf(fA, a.w, fB * b.w);
        }
        size_t base = (size_t)d * HW + hw0;
        float* oy = out + (size_t)(CC + c0) * NDHW + base;
        float* ox = out + (size_t)c0 * NDHW + base;
        __stcs((float4*)(oy + 0 * (size_t)NDHW), make_float4(oc[0][0], oc[0][1], oc[0][2], oc[0][3]));
        __stcs((float4*)(oy + 1 * (size_t)NDHW), make_float4(oc[1][0], oc[1][1], oc[1][2], oc[1][3]));
        __stcs((float4*)(oy + 2 * (size_t)NDHW), make_float4(oc[2][0], oc[2][1], oc[2][2], oc[2][3]));
        __stcs((float4*)(oy + 3 * (size_t)NDHW), make_float4(oc[3][0], oc[3][1], oc[3][2], oc[3][3]));
        #pragma unroll
        for (int c = 0; c < 4; c++) {
            float4 xv = *(const float4*)(x + (size_t)(c0 + c) * HW + hw0);
            __stcs((float4*)(ox + (size_t)c * NDHW), xv);
        }
    }
}

extern "C" void kernel_launch(void* const* d_in, const int* in_sizes, int n_in,
                              void* d_out, int out_size) {
    const float* x     = (const float*)d_in[0];
    const float* y     = (const float*)d_in[1];
    const float* depth = (const float*)d_in[2];
    float* out = (float*)d_out;

    prologue_kernel<<<(4 * HW) / 256, 256>>>(y, depth);
    dim3 grid(4 * (WW / WTILE), HH);   // chunk fastest
    fused_cv_kernel<<<grid, 256>>>(x, out);
}

// round 17
// speedup vs baseline: 1.0871x; 1.0871x over previous
#include <cuda_runtime.h>
#include <math.h>

#define HH 256
#define WW 512
#define CC 16
#define ND 32
#define HW (HH * WW)
#define NDHW (ND * HW)
#define BASELINE_V 0.24f
#define WTILE 64
#define SROW 67            // padded smem row stride in float4
#define MAX_ROWS 46

// Horizontally pre-interpolated y, 4 channel-chunk planes
__device__ float4 g_Z[4 * HW];
// Precomputed vertical sample position per (d,h,w)
__device__ float g_iy[NDHW];

// iy via cancellation-free identity: atan(u) - theta = atan(B*cos/(d + B*sin))
__device__ __forceinline__ float iy_fast(float dep, float Bs, float Bc, float hf)
{
    float dth = atanf(__fdividef(Bc, dep + Bs));             // > 0, small arg
    float ypx = hf + dth * ((float)HH / 3.14159265358979323846f);
    return ypx * ((float)HH / ((float)HH - 1.0f)) - 0.5f;
}

__device__ __forceinline__ float iy_exact(float dep, float Bs, float Bc, float hf)
{
    float dth = atanf(Bc / (dep + Bs));
    float ypx = hf + dth * ((float)HH / 3.14159265358979323846f);
    return ypx * ((float)HH / ((float)HH - 1.0f)) - 0.5f;
}

// ---------------- Kernel 1: merged prologue ----------------
// 4*HW threads: thread (chunk, p) does hinterp of its chunk at pixel p,
// plus iy for the 8 disparities d in [chunk*8, chunk*8+8).
__global__ __launch_bounds__(256) void prologue_kernel(const float* __restrict__ y,
                                                       const float* __restrict__ depth)
{
    int t = blockIdx.x * 256 + threadIdx.x;   // 4*HW threads
    int p = t & (HW - 1);
    int chunk = t >> 17;
    int w = p & (WW - 1);
    int h = p >> 9;
    int rbase = p - w;

    const float PI = 3.14159265358979323846f;
    float hf = (float)h;
    float theta = (hf + 0.5f) * (PI / (float)HH) - 0.5f * PI;
    float st, ct;
    sincosf(theta, &st, &ct);
    float Bs = BASELINE_V * st, Bc = BASELINE_V * ct;

    // --- horizontal interp for this chunk ---
    float ix = (float)w * ((float)WW / ((float)WW - 1.0f)) - 0.5f;
    float fx0 = floorf(ix);
    float wx  = ix - fx0;
    int xi0 = (int)fx0, xi1 = xi0 + 1;
    float w0x = (xi0 >= 0 && xi0 < WW) ? (1.0f - wx) : 0.0f;
    float w1x = (xi1 >= 0 && xi1 < WW) ? wx : 0.0f;
    int xc0 = min(max(xi0, 0), WW - 1);
    int xc1 = min(max(xi1, 0), WW - 1);

    float v[4];
    #pragma unroll
    for (int c = 0; c < 4; c++) {
        const float* yc = y + (size_t)(chunk * 4 + c) * HW + rbase;
        v[c] = w0x * __ldg(yc + xc0) + w1x * __ldg(yc + xc1);
    }
    g_Z[chunk * HW + p] = make_float4(v[0], v[1], v[2], v[3]);

    // --- iy for this chunk's 8 disparities ---
    int d0 = chunk * 8;
    #pragma unroll
    for (int k = 0; k < 8; k++) {
        float dep = __ldg(depth + (size_t)(d0 + k) * HW + p);
        g_iy[(size_t)(d0 + k) * HW + p] = iy_fast(dep, Bs, Bc, hf);
    }
}

// ---------------- Kernel 2: smem-staged fused kernel (R9 config) ----------------
// grid (4 chunks * 8 wtiles, HH). Block 256 = 16 wg (4 w) x 16 dg (2 d each).
__global__ __launch_bounds__(256, 4) void fused_cv_kernel(const float* __restrict__ x,
                                                          float* __restrict__ out)
{
    __shared__ float4 s_Z[MAX_ROWS * SROW];   // ~49.3 KB -> 4 CTAs/SM

    int chunk = blockIdx.x & 3;
    int wt    = blockIdx.x >> 2;
    int h     = blockIdx.y;
    int wg    = threadIdx.x & 15;
    int dg    = threadIdx.x >> 4;              // 0..15
    int wbase = wt * WTILE;
    int w0    = wbase + wg * 4;
    int c0    = chunk * 4;

    const float PI = 3.14159265358979323846f;
    float hf = (float)h;
    float theta = (hf + 0.5f) * (PI / (float)HH) - 0.5f * PI;
    float st, ct;
    sincosf(theta, &st, &ct);
    float Bs = BASELINE_V * st, Bc = BASELINE_V * ct;

    // row range for depth in [0.5, 8] (iy monotone decreasing in depth)
    float iy_min = iy_exact(8.0f, Bs, Bc, hf);
    float iy_max = iy_exact(0.5f, Bs, Bc, hf);
    int r_lo = min(max((int)floorf(iy_min) - 1, 0), HH - 1);
    int r_hi = min(max((int)floorf(iy_max) + 2, 0), HH - 1);
    int nrows = min(r_hi - r_lo + 1, MAX_ROWS);

    int hw0 = h * WW + w0;

    // prefetch iy for both d's (latency overlaps with staging below)
    float4 iy4_0 = *(const float4*)(g_iy + (size_t)(dg * 2 + 0) * HW + hw0);
    float4 iy4_1 = *(const float4*)(g_iy + (size_t)(dg * 2 + 1) * HW + hw0);

    // cooperative staging of Z rows for this wtile
    const float4* __restrict__ plane = g_Z + (size_t)chunk * HW;
    for (int i = threadIdx.x; i < nrows * WTILE; i += 256) {
        int row = i >> 6;
        int col = i & (WTILE - 1);
        s_Z[row * SROW + col] = __ldg(plane + (size_t)(r_lo + row) * WW + wbase + col);
    }

    // vertical interp params (ALU overlaps other warps' staging)
    float wA[2][4], wB[2][4];
    int   o0[2][4], o1[2][4];
    #pragma unroll
    for (int k = 0; k < 2; k++) {
        float4 iy4 = k ? iy4_1 : iy4_0;
        #pragma unroll
        for (int j = 0; j < 4; j++) {
            float iy = (j == 0) ? iy4.x : (j == 1) ? iy4.y : (j == 2) ? iy4.z : iy4.w;
            float fy0 = floorf(iy);
            float wy  = iy - fy0;
            int yi0 = (int)fy0, yi1 = yi0 + 1;
            wA[k][j] = (yi0 >= 0 && yi0 < HH) ? (1.0f - wy) : 0.0f;
            wB[k][j] = (yi1 >= 0 && yi1 < HH) ? wy : 0.0f;
            int yc0 = min(max(yi0, 0), HH - 1);
            int yc1 = min(max(yi1, 0), HH - 1);
            int ry0 = min(max(yc0 - r_lo, 0), nrows - 1);
            int ry1 = min(max(yc1 - r_lo, 0), nrows - 1);
            o0[k][j] = ry0 * SROW + wg * 4 + j;
            o1[k][j] = ry1 * SROW + wg * 4 + j;
        }
    }

    __syncthreads();

    #pragma unroll
    for (int k = 0; k < 2; k++) {
        int d = dg * 2 + k;
        float oc[4][4];
        #pragma unroll
        for (int j = 0; j < 4; j++) {
            float4 a = s_Z[o0[k][j]];
            float4 b = s_Z[o1[k][j]];
            float fA = wA[k][j], fB = wB[k][j];
            oc[0][j] = fmaf(fA, a.x, fB * b.x);
            oc[1][j] = fmaf(fA, a.y, fB * b.y);
            oc[2][j] = fmaf(fA, a.z, fB * b.z);
            oc[3][j] = fmaf(fA, a.w, fB * b.w);
        }
        size_t base = (size_t)d * HW + hw0;
        float* oy = out + (size_t)(CC + c0) * NDHW + base;
        float* ox = out + (size_t)c0 * NDHW + base;
        __stcs((float4*)(oy + 0 * (size_t)NDHW), make_float4(oc[0][0], oc[0][1], oc[0][2], oc[0][3]));
        __stcs((float4*)(oy + 1 * (size_t)NDHW), make_float4(oc[1][0], oc[1][1], oc[1][2], oc[1][3]));
        __stcs((float4*)(oy + 2 * (size_t)NDHW), make_float4(oc[2][0], oc[2][1], oc[2][2], oc[2][3]));
        __stcs((float4*)(oy + 3 * (size_t)NDHW), make_float4(oc[3][0], oc[3][1], oc[3][2], oc[3][3]));
        #pragma unroll
        for (int c = 0; c < 4; c++) {
            float4 xv = *(const float4*)(x + (size_t)(c0 + c) * HW + hw0);
            __stcs((float4*)(ox + (size_t)c * NDHW), xv);
        }
    }
}

extern "C" void kernel_launch(void* const* d_in, const int* in_sizes, int n_in,
                              void* d_out, int out_size) {
    const float* x     = (const float*)d_in[0];
    const float* y     = (const float*)d_in[1];
    const float* depth = (const float*)d_in[2];
    float* out = (float*)d_out;

    prologue_kernel<<<(4 * HW) / 256, 256>>>(y, depth);
    dim3 grid(4 * (WW / WTILE), HH);   // chunk fastest
    fused_cv_kernel<<<grid, 256>>>(x, out);
}